// round 4
// baseline (speedup 1.0000x reference)
#include <cuda_runtime.h>
#include <math.h>

#define D_FEAT 8192
#define T_RES  2048
#define ORDER  16
#define DTAU   0.08f
#define REG    0.0001f
#define EPS_C  1e-15f

#define NPART  128   // blocks in column kernels (each owns 64 columns)

// ---------------- device scratch (no allocations allowed) ----------------
__device__ float g_s[ORDER * T_RES];      // s_j = R q_j, j = 0..15
__device__ float g_sf[T_RES];             // R f
__device__ float g_Q[ORDER * D_FEAT];     // Lanczos basis Q[0..15]
__device__ float g_wf[D_FEAT];            // current unnormalized next basis vector
__device__ float g_nrm2_part[NPART];      // per-block partials of ||wf||^2
__device__ float g_b[ORDER + 1];          // g_b[0] = ||F||, g_b[j] = beta[j-1] (j>=1)
__device__ float g_alpha[ORDER];
__device__ float g_coeffs[ORDER];

// ---------------- prologue: sf = R f ----------------
__global__ void k_rowgemv_f(const float* __restrict__ R, const float* __restrict__ f) {
    int tx = threadIdx.x, lane = tx & 31;
    int wglob = (blockIdx.x * blockDim.x + tx) >> 5;
    int nw = (gridDim.x * blockDim.x) >> 5;
    const float4* f4 = (const float4*)f;
    for (int r = wglob; r < T_RES; r += nw) {
        const float4* R4 = (const float4*)(R + (size_t)r * D_FEAT);
        float a0 = 0.f, a1 = 0.f, a2 = 0.f, a3 = 0.f;
        #pragma unroll 4
        for (int i = lane; i < D_FEAT / 4; i += 32) {
            float4 rr = R4[i], ww = f4[i];
            a0 = fmaf(rr.x, ww.x, a0); a1 = fmaf(rr.y, ww.y, a1);
            a2 = fmaf(rr.z, ww.z, a2); a3 = fmaf(rr.w, ww.w, a3);
        }
        float acc = (a0 + a1) + (a2 + a3);
        #pragma unroll
        for (int o = 16; o; o >>= 1) acc += __shfl_xor_sync(0xffffffffu, acc, o);
        if (lane == 0) g_sf[r] = acc;
    }
}

// ---------------- prologue: F = (R^T sf) + E f ; write wf=F, nrm2 partials -----
__global__ void k_prologue_col(const float* __restrict__ R, const float* __restrict__ f) {
    __shared__ float sh_w1[8], sh_w2[8], sh_nr[8];
    __shared__ float sh_E;
    __shared__ float4 sh_acc[256];
    int tx = threadIdx.x, lane = tx & 31, w = tx >> 5;

    // ||sf||^2 and ||f||^2 (per-block redundant, deterministic)
    float p = 0.f;
    for (int t = tx; t < T_RES; t += 256) { float v = g_sf[t]; p = fmaf(v, v, p); }
    #pragma unroll
    for (int o = 16; o; o >>= 1) p += __shfl_xor_sync(0xffffffffu, p, o);
    if (lane == 0) sh_w1[w] = p;
    float q = 0.f;
    for (int d = tx; d < D_FEAT; d += 256) { float v = f[d]; q = fmaf(v, v, q); }
    #pragma unroll
    for (int o = 16; o; o >>= 1) q += __shfl_xor_sync(0xffffffffu, q, o);
    if (lane == 0) sh_w2[w] = q;
    __syncthreads();
    if (tx == 0) {
        float ssf = 0.f, ff = 0.f;
        #pragma unroll
        for (int i = 0; i < 8; i++) { ssf += sh_w1[i]; ff += sh_w2[i]; }
        sh_E = -ssf / (ff + EPS_C);      // E = f.Hf/(f.f+eps), f.Hf = -||sf||^2
    }
    __syncthreads();
    float E = sh_E;

    // u[d] = sum_t R[t][d]*sf[t]   (column GEMV, t split across 16 chunks)
    int g = tx & 15, s = tx >> 4;
    int col4 = blockIdx.x * 16 + g;
    const float4* R4 = (const float4*)R;
    float4 acc = make_float4(0.f, 0.f, 0.f, 0.f);
    int t0 = s * 128;
    #pragma unroll 8
    for (int t = t0; t < t0 + 128; ++t) {
        float sv = g_sf[t];
        float4 rv = R4[(size_t)t * (D_FEAT / 4) + col4];
        acc.x = fmaf(rv.x, sv, acc.x); acc.y = fmaf(rv.y, sv, acc.y);
        acc.z = fmaf(rv.z, sv, acc.z); acc.w = fmaf(rv.w, sv, acc.w);
    }
    sh_acc[tx] = acc;
    __syncthreads();

    float nrm_p = 0.f;
    if (tx < 64) {
        const float* shf = (const float*)sh_acc;
        float u = 0.f;
        #pragma unroll
        for (int k = 0; k < 16; k++) u += shf[k * 64 + tx];
        int col = blockIdx.x * 64 + tx;
        float F = fmaf(E, f[col], u);   // F = u + E f  ( = -(Hf - E f) )
        g_wf[col] = F;
        nrm_p = F * F;
    }
    #pragma unroll
    for (int o = 16; o; o >>= 1) nrm_p += __shfl_xor_sync(0xffffffffu, nrm_p, o);
    if (lane == 0) sh_nr[w] = nrm_p;
    __syncthreads();
    if (tx == 0) {
        float n = 0.f;
        #pragma unroll
        for (int i = 0; i < 8; i++) n += sh_nr[i];
        g_nrm2_part[blockIdx.x] = n;
    }
}

// ---------------- iteration phase A: s_j = R * (wf / b) ----------------
__global__ void k_A(const float* __restrict__ R, int j) {
    __shared__ float sh[128];
    __shared__ float sh_invb;
    int tx = threadIdx.x, lane = tx & 31;

    if (tx < 128) sh[tx] = g_nrm2_part[tx];
    __syncthreads();
    #pragma unroll
    for (int st = 64; st; st >>= 1) { if (tx < st) sh[tx] += sh[tx + st]; __syncthreads(); }
    if (tx == 0) {
        float b = sqrtf(sh[0]);
        if (blockIdx.x == 0) g_b[j] = b;
        sh_invb = 1.0f / fmaxf(b, 1e-30f);
    }
    __syncthreads();
    float invb = sh_invb;

    int wglob = (blockIdx.x * blockDim.x + tx) >> 5;
    int nw = (gridDim.x * blockDim.x) >> 5;
    const float4* w4 = (const float4*)g_wf;
    for (int r = wglob; r < T_RES; r += nw) {
        const float4* R4 = (const float4*)(R + (size_t)r * D_FEAT);
        float a0 = 0.f, a1 = 0.f, a2 = 0.f, a3 = 0.f;
        #pragma unroll 4
        for (int i = lane; i < D_FEAT / 4; i += 32) {
            float4 rr = R4[i], ww = w4[i];
            a0 = fmaf(rr.x, ww.x, a0); a1 = fmaf(rr.y, ww.y, a1);
            a2 = fmaf(rr.z, ww.z, a2); a3 = fmaf(rr.w, ww.w, a3);
        }
        float acc = (a0 + a1) + (a2 + a3);
        #pragma unroll
        for (int o = 16; o; o >>= 1) acc += __shfl_xor_sync(0xffffffffu, acc, o);
        if (lane == 0) g_s[j * T_RES + r] = acc * invb;
    }
}

// ---- iteration phase B: c_k = s_k.s_j ; w = -R^T s_j + sum c_k Q[k];
//      materialize Q[j] = wf*invb ; write new wf ; nrm2 partials; alpha[j] ----
__global__ void k_B(const float* __restrict__ R, int j, int last) {
    __shared__ float sh_c[ORDER];
    __shared__ float4 sh_acc[256];
    __shared__ float sh_nr[8];
    int tx = threadIdx.x, lane = tx & 31, w = tx >> 5;
    const float* sj = g_s + (size_t)j * T_RES;
    float invb = 1.0f / fmaxf(g_b[j], 1e-30f);

    // dots c_k = s_k . s_j for k = 0..j (warps strided over k)
    for (int k = w; k <= j; k += 8) {
        const float* sk = g_s + (size_t)k * T_RES;
        float p = 0.f;
        #pragma unroll 4
        for (int t = lane; t < T_RES; t += 32) p = fmaf(sk[t], sj[t], p);
        #pragma unroll
        for (int o = 16; o; o >>= 1) p += __shfl_xor_sync(0xffffffffu, p, o);
        if (lane == 0) sh_c[k] = p;
    }
    __syncthreads();

    if (blockIdx.x == 0 && tx == 0) g_alpha[j] = -sh_c[j];  // alpha = -||s_j||^2

    if (last) {  // only need Q[j] materialized and alpha[j]
        if (tx < 64) {
            int col = blockIdx.x * 64 + tx;
            g_Q[(size_t)j * D_FEAT + col] = g_wf[col] * invb;
        }
        return;
    }

    // w[d] = -sum_t R[t][d] * s_j[t]
    int g = tx & 15, s = tx >> 4;
    int col4 = blockIdx.x * 16 + g;
    const float4* R4 = (const float4*)R;
    float4 acc = make_float4(0.f, 0.f, 0.f, 0.f);
    int t0 = s * 128;
    #pragma unroll 8
    for (int t = t0; t < t0 + 128; ++t) {
        float sv = sj[t];
        float4 rv = R4[(size_t)t * (D_FEAT / 4) + col4];
        acc.x = fmaf(rv.x, sv, acc.x); acc.y = fmaf(rv.y, sv, acc.y);
        acc.z = fmaf(rv.z, sv, acc.z); acc.w = fmaf(rv.w, sv, acc.w);
    }
    sh_acc[tx] = acc;
    __syncthreads();

    float nrm_p = 0.f;
    if (tx < 64) {
        const float* shf = (const float*)sh_acc;
        float u = 0.f;
        #pragma unroll
        for (int k = 0; k < 16; k++) u += shf[k * 64 + tx];
        int col = blockIdx.x * 64 + tx;
        float qv = g_wf[col] * invb;
        g_Q[(size_t)j * D_FEAT + col] = qv;      // materialize current basis vector
        float wv = -u;
        for (int k = 0; k < j; k++)              // reorth: w + sum_k c_k Q[k]
            wv = fmaf(sh_c[k], g_Q[(size_t)k * D_FEAT + col], wv);
        wv = fmaf(sh_c[j], qv, wv);
        g_wf[col] = wv;
        nrm_p = wv * wv;
    }
    #pragma unroll
    for (int o = 16; o; o >>= 1) nrm_p += __shfl_xor_sync(0xffffffffu, nrm_p, o);
    if (lane == 0) sh_nr[w] = nrm_p;
    __syncthreads();
    if (tx == 0) {
        float n = 0.f;
        #pragma unroll
        for (int i = 0; i < 8; i++) n += sh_nr[i];
        g_nrm2_part[blockIdx.x] = n;
    }
}

// -------- coeffs = normF * exp(-T*DTAU) e0 via Taylor (double, 1 thread) ------
__global__ void k_expmT() {
    if (threadIdx.x == 0 && blockIdx.x == 0) {
        double a[ORDER], bb[ORDER - 1], y[ORDER], v[ORDER], nv[ORDER];
        for (int i = 0; i < ORDER; i++) a[i] = (double)g_alpha[i];
        for (int i = 0; i < ORDER - 1; i++) bb[i] = (double)g_b[i + 1];
        double normF = (double)g_b[0];
        for (int i = 0; i < ORDER; i++) { y[i] = (i == 0) ? 1.0 : 0.0; v[i] = y[i]; }
        for (int k = 1; k <= 48; k++) {
            double sc = -(double)DTAU / (double)k;
            for (int i = 0; i < ORDER; i++) {
                double t = a[i] * v[i];
                if (i > 0) t += bb[i - 1] * v[i - 1];
                if (i < ORDER - 1) t += bb[i] * v[i + 1];
                nv[i] = t * sc;
            }
            for (int i = 0; i < ORDER; i++) { v[i] = nv[i]; y[i] += nv[i]; }
        }
        for (int i = 0; i < ORDER; i++) g_coeffs[i] = (float)(normF * y[i]);
    }
}

// -------- dtheta[p] = D[p].(sum_l coeffs[l] Q[l]) / (||D[p]||^2 + REG) --------
__global__ void k_final(const float* __restrict__ Dm, float* __restrict__ out) {
    __shared__ float sh_a[8], sh_d[8];
    int p = blockIdx.x;
    int tx = threadIdx.x, lane = tx & 31, w = tx >> 5;
    float cf[ORDER];
    #pragma unroll
    for (int l = 0; l < ORDER; l++) cf[l] = g_coeffs[l];
    const float* Dp = Dm + (size_t)p * D_FEAT;
    float acc = 0.f, den = 0.f;
    for (int d = tx; d < D_FEAT; d += 256) {
        float dir = 0.f;
        #pragma unroll
        for (int l = 0; l < ORDER; l++) dir = fmaf(cf[l], g_Q[(size_t)l * D_FEAT + d], dir);
        float dv = Dp[d];
        acc = fmaf(dv, dir, acc);
        den = fmaf(dv, dv, den);
    }
    #pragma unroll
    for (int o = 16; o; o >>= 1) {
        acc += __shfl_xor_sync(0xffffffffu, acc, o);
        den += __shfl_xor_sync(0xffffffffu, den, o);
    }
    if (lane == 0) { sh_a[w] = acc; sh_d[w] = den; }
    __syncthreads();
    if (tx == 0) {
        float A = 0.f, Dd = 0.f;
        #pragma unroll
        for (int i = 0; i < 8; i++) { A += sh_a[i]; Dd += sh_d[i]; }
        out[p] = A / (Dd + REG);
    }
}

// --------------------------------- launcher ----------------------------------
extern "C" void kernel_launch(void* const* d_in, const int* in_sizes, int n_in,
                              void* d_out, int out_size) {
    (void)out_size;
    const float* f = nullptr;
    const float* R = nullptr;
    const float* Dm = nullptr;
    for (int i = 0; i < n_in; i++) {
        if (in_sizes[i] == D_FEAT)                f  = (const float*)d_in[i];
        else if (in_sizes[i] == T_RES * D_FEAT)   R  = (const float*)d_in[i];
        else if (in_sizes[i] == ORDER * D_FEAT)   Dm = (const float*)d_in[i];
    }

    k_rowgemv_f<<<NPART, 256>>>(R, f);
    k_prologue_col<<<NPART, 256>>>(R, f);
    for (int j = 0; j < ORDER; j++) {
        k_A<<<NPART, 256>>>(R, j);
        k_B<<<NPART, 256>>>(R, j, (j == ORDER - 1) ? 1 : 0);
    }
    k_expmT<<<1, 32>>>();
    k_final<<<ORDER, 256>>>(Dm, (float*)d_out);
}

// round 8
// speedup vs baseline: 1.9006x; 1.9006x over previous
#include <cuda_runtime.h>
#include <math.h>

#define D_FEAT 8192
#define T_RES  2048
#define ORDER  16
#define DTAU   0.08
#define REG    0.0001f
#define EPS_C  1e-15f

#define ROW_BLOCKS 256   // row kernels: 8 warps/block, one row per warp
#define COL_BLOCKS 512   // col kernels: 16 columns per block
#define NW 256           // threads per block everywhere

// ---------------- device scratch (no allocations allowed) ----------------
__device__ float g_s[ORDER * T_RES];          // s_j = R q_j
__device__ float g_sf[T_RES];                 // R f
__device__ float g_Q[ORDER * D_FEAT];         // Lanczos basis
__device__ float g_wf[D_FEAT];                // current unnormalized basis vector
__device__ float g_nrm2_part[COL_BLOCKS];     // ||wf||^2 partials (per col-block)
__device__ float g_cpart[ROW_BLOCKS * ORDER]; // per-row-block partials of c_k = s_k.s_j
__device__ float g_b[ORDER + 1];              // g_b[0]=||F||, g_b[j]=beta[j-1]
__device__ float g_alpha[ORDER];
__device__ float g_coeffs[ORDER];

__device__ __forceinline__ void fma4(float4& a, const float4 r, const float4 v) {
    a.x = fmaf(r.x, v.x, a.x); a.y = fmaf(r.y, v.y, a.y);
    a.z = fmaf(r.z, v.z, a.z); a.w = fmaf(r.w, v.w, a.w);
}

// ================= prologue row: sf = R f =================
__global__ void k_row_f(const float* __restrict__ R, const float* __restrict__ f) {
    int tx = threadIdx.x, lane = tx & 31, w = tx >> 5;
    int r = blockIdx.x * 8 + w;
    const float4* R4 = (const float4*)(R + (size_t)r * D_FEAT);
    const float4* f4 = (const float4*)f;
    float4 aA = make_float4(0.f,0.f,0.f,0.f), aB = aA;
    #pragma unroll 8
    for (int it = 0; it < 64; it += 2) {
        int i0 = it * 32 + lane, i1 = i0 + 32;
        fma4(aA, R4[i0], f4[i0]);
        fma4(aB, R4[i1], f4[i1]);
    }
    float acc = (aA.x + aA.y) + (aA.z + aA.w) + (aB.x + aB.y) + (aB.z + aB.w);
    #pragma unroll
    for (int o = 16; o; o >>= 1) acc += __shfl_xor_sync(0xffffffffu, acc, o);
    if (lane == 0) g_sf[r] = acc;
}

// ========= prologue col: F = R^T sf + E f ; wf = F ; ||F||^2 partials =========
__global__ void k_prologue_col(const float* __restrict__ R, const float* __restrict__ f) {
    __shared__ float s_sm[T_RES];
    __shared__ float4 sh[NW];
    __shared__ float sh_r1[8], sh_r2[8];
    __shared__ float shE;
    int tx = threadIdx.x, lane = tx & 31, w = tx >> 5;
    const float4* f4 = (const float4*)f;

    // stage sf into smem; per-block full ||sf||^2 and ||f||^2 (deterministic)
    float ssf = 0.f;
    for (int i = tx; i < T_RES / 4; i += NW) {
        float4 v = ((const float4*)g_sf)[i];
        ((float4*)s_sm)[i] = v;
        ssf = fmaf(v.x, v.x, fmaf(v.y, v.y, fmaf(v.z, v.z, fmaf(v.w, v.w, ssf))));
    }
    float ff = 0.f;
    for (int i = tx; i < D_FEAT / 4; i += NW) {
        float4 v = f4[i];
        ff = fmaf(v.x, v.x, fmaf(v.y, v.y, fmaf(v.z, v.z, fmaf(v.w, v.w, ff))));
    }
    #pragma unroll
    for (int o = 16; o; o >>= 1) {
        ssf += __shfl_xor_sync(0xffffffffu, ssf, o);
        ff  += __shfl_xor_sync(0xffffffffu, ff, o);
    }
    if (lane == 0) { sh_r1[w] = ssf; sh_r2[w] = ff; }
    __syncthreads();
    if (tx == 0) {
        float a = 0.f, b = 0.f;
        #pragma unroll
        for (int i = 0; i < 8; i++) { a += sh_r1[i]; b += sh_r2[i]; }
        shE = -a / (b + EPS_C);   // E = f.Hf/(f.f+eps), f.Hf = -||sf||^2
    }
    __syncthreads();

    // u[col] = sum_t R[t][col] * sf[t]
    int g = tx & 3, s = tx >> 2;
    const float4* R4 = (const float4*)R;
    size_t cbase = (size_t)blockIdx.x * 4 + g;
    float4 aA = make_float4(0.f,0.f,0.f,0.f), aB = aA;
    #pragma unroll 8
    for (int it = 0; it < 32; it += 2) {
        int t0 = it * 64 + s, t1 = t0 + 64;
        float s0 = s_sm[t0], s1 = s_sm[t1];
        float4 r0 = R4[(size_t)t0 * (D_FEAT/4) + cbase];
        float4 r1 = R4[(size_t)t1 * (D_FEAT/4) + cbase];
        aA.x = fmaf(r0.x, s0, aA.x); aA.y = fmaf(r0.y, s0, aA.y);
        aA.z = fmaf(r0.z, s0, aA.z); aA.w = fmaf(r0.w, s0, aA.w);
        aB.x = fmaf(r1.x, s1, aB.x); aB.y = fmaf(r1.y, s1, aB.y);
        aB.z = fmaf(r1.z, s1, aB.z); aB.w = fmaf(r1.w, s1, aB.w);
    }
    aA.x += aB.x; aA.y += aB.y; aA.z += aB.z; aA.w += aB.w;
    sh[tx] = aA;
    #pragma unroll
    for (int off = 128; off >= 4; off >>= 1) {
        __syncthreads();
        if (tx < off) {
            float4 a = sh[tx], b2 = sh[tx + off];
            a.x += b2.x; a.y += b2.y; a.z += b2.z; a.w += b2.w;
            sh[tx] = a;
        }
    }
    __syncthreads();

    float nrm = 0.f;
    if (tx < 16) {
        float u = ((const float*)sh)[tx];
        int col = blockIdx.x * 16 + tx;
        float F = fmaf(shE, f[col], u);
        g_wf[col] = F;
        nrm = F * F;
    }
    if (tx < 32) {
        #pragma unroll
        for (int o = 8; o; o >>= 1) nrm += __shfl_xor_sync(0xffffffffu, nrm, o);
        if (tx == 0) g_nrm2_part[blockIdx.x] = nrm;
    }
}

// ===== k_A: b=||wf||; s_j = R*(wf/b); c-partials for c_k = s_k.s_j =====
__global__ void k_A(const float* __restrict__ R, int j) {
    __shared__ float sh_r[8];
    __shared__ float sh_invb;
    __shared__ float sh_cp[8][16];
    int tx = threadIdx.x, lane = tx & 31, w = tx >> 5;

    float p = g_nrm2_part[tx] + g_nrm2_part[tx + NW];   // COL_BLOCKS = 2*NW
    #pragma unroll
    for (int o = 16; o; o >>= 1) p += __shfl_xor_sync(0xffffffffu, p, o);
    if (lane == 0) sh_r[w] = p;
    __syncthreads();
    if (tx == 0) {
        float n = 0.f;
        #pragma unroll
        for (int i = 0; i < 8; i++) n += sh_r[i];
        float b = sqrtf(n);
        if (blockIdx.x == 0) g_b[j] = b;
        sh_invb = 1.0f / fmaxf(b, 1e-30f);
    }
    __syncthreads();
    float invb = sh_invb;

    int r = blockIdx.x * 8 + w;
    const float4* R4 = (const float4*)(R + (size_t)r * D_FEAT);
    const float4* w4 = (const float4*)g_wf;
    float4 aA = make_float4(0.f,0.f,0.f,0.f), aB = aA;
    #pragma unroll 8
    for (int it = 0; it < 64; it += 2) {
        int i0 = it * 32 + lane, i1 = i0 + 32;
        fma4(aA, R4[i0], w4[i0]);
        fma4(aB, R4[i1], w4[i1]);
    }
    float acc = (aA.x + aA.y) + (aA.z + aA.w) + (aB.x + aB.y) + (aB.z + aB.w);
    #pragma unroll
    for (int o = 16; o; o >>= 1) acc += __shfl_xor_sync(0xffffffffu, acc, o);
    float sjr = acc * invb;              // all lanes hold s_j[r]
    if (lane == 0) g_s[j * T_RES + r] = sjr;

    float cp = 0.f;
    if (lane <= j) {                     // lane k contributes s_k[r]*s_j[r]
        float skr = (lane == j) ? sjr : g_s[lane * T_RES + r];
        cp = skr * sjr;
    }
    if (lane < 16) sh_cp[w][lane] = cp;
    __syncthreads();
    if (tx < 16) {
        float c = 0.f;
        #pragma unroll
        for (int i = 0; i < 8; i++) c += sh_cp[i][tx];
        g_cpart[blockIdx.x * 16 + tx] = c;
    }
}

// ===== k_B: reduce c; w = -R^T s_j + sum c_k Q[k]; Q[j]=wf/b; new wf =====
__global__ void k_B(const float* __restrict__ R, int j, int last) {
    __shared__ float s_sm[T_RES];
    __shared__ float4 sh[NW];
    __shared__ float sh_c[ORDER];
    int tx = threadIdx.x;
    float invb = 1.0f / fmaxf(g_b[j], 1e-30f);

    // reduce c-partials: k = tx>>4, i = tx&15 (i within warp -> shfl ok)
    {
        int k = tx >> 4, i = tx & 15;
        float c = 0.f;
        #pragma unroll
        for (int m = 0; m < ROW_BLOCKS / 16; m++)
            c += g_cpart[(m * 16 + i) * 16 + k];
        #pragma unroll
        for (int o = 8; o; o >>= 1) c += __shfl_xor_sync(0xffffffffu, c, o);
        if (i == 0) sh_c[k] = c;
    }
    // stage s_j into smem
    const float4* sj4 = (const float4*)(g_s + (size_t)j * T_RES);
    for (int i = tx; i < T_RES / 4; i += NW) ((float4*)s_sm)[i] = sj4[i];
    __syncthreads();

    if (blockIdx.x == 0 && tx == 0) g_alpha[j] = -sh_c[j];

    if (last) {
        if (tx < 16) {
            int col = blockIdx.x * 16 + tx;
            g_Q[(size_t)j * D_FEAT + col] = g_wf[col] * invb;
        }
        return;
    }

    // u[col] = sum_t R[t][col] * s_j[t]
    int g = tx & 3, s = tx >> 2;
    const float4* R4 = (const float4*)R;
    size_t cbase = (size_t)blockIdx.x * 4 + g;
    float4 aA = make_float4(0.f,0.f,0.f,0.f), aB = aA;
    #pragma unroll 8
    for (int it = 0; it < 32; it += 2) {
        int t0 = it * 64 + s, t1 = t0 + 64;
        float s0 = s_sm[t0], s1 = s_sm[t1];
        float4 r0 = R4[(size_t)t0 * (D_FEAT/4) + cbase];
        float4 r1 = R4[(size_t)t1 * (D_FEAT/4) + cbase];
        aA.x = fmaf(r0.x, s0, aA.x); aA.y = fmaf(r0.y, s0, aA.y);
        aA.z = fmaf(r0.z, s0, aA.z); aA.w = fmaf(r0.w, s0, aA.w);
        aB.x = fmaf(r1.x, s1, aB.x); aB.y = fmaf(r1.y, s1, aB.y);
        aB.z = fmaf(r1.z, s1, aB.z); aB.w = fmaf(r1.w, s1, aB.w);
    }
    aA.x += aB.x; aA.y += aB.y; aA.z += aB.z; aA.w += aB.w;
    sh[tx] = aA;
    #pragma unroll
    for (int off = 128; off >= 4; off >>= 1) {
        __syncthreads();
        if (tx < off) {
            float4 a = sh[tx], b2 = sh[tx + off];
            a.x += b2.x; a.y += b2.y; a.z += b2.z; a.w += b2.w;
            sh[tx] = a;
        }
    }
    __syncthreads();

    float nrm = 0.f;
    if (tx < 16) {
        float u = ((const float*)sh)[tx];
        int col = blockIdx.x * 16 + tx;
        float qv = g_wf[col] * invb;
        g_Q[(size_t)j * D_FEAT + col] = qv;
        float wv = -u;
        for (int k = 0; k < j; k++)
            wv = fmaf(sh_c[k], g_Q[(size_t)k * D_FEAT + col], wv);
        wv = fmaf(sh_c[j], qv, wv);
        g_wf[col] = wv;
        nrm = wv * wv;
    }
    if (tx < 32) {
        #pragma unroll
        for (int o = 8; o; o >>= 1) nrm += __shfl_xor_sync(0xffffffffu, nrm, o);
        if (tx == 0) g_nrm2_part[blockIdx.x] = nrm;
    }
}

// ====== coeffs = normF * exp(-T*DTAU) e0 : lane-parallel Taylor (double) ======
__global__ void k_expmT() {
    int lane = threadIdx.x & 31;
    double a = 0.0, bl = 0.0, bu = 0.0;
    if (lane < ORDER) a = (double)g_alpha[lane];
    if (lane >= 1 && lane < ORDER) bl = (double)g_b[lane];        // beta[lane-1]
    if (lane < ORDER - 1) bu = (double)g_b[lane + 1];             // beta[lane]
    double v = (lane == 0) ? 1.0 : 0.0, y = v;
    for (int k = 1; k <= 40; k++) {
        double vp = __shfl_up_sync(0xffffffffu, v, 1);
        double vn = __shfl_down_sync(0xffffffffu, v, 1);
        double t = a * v + bl * vp + bu * vn;
        v = t * (-DTAU / (double)k);
        y += v;
    }
    if (lane < ORDER) g_coeffs[lane] = (float)((double)g_b[0] * y);
}

// ====== dtheta[p] = D[p].(sum_l coeffs[l] Q[l]) / (||D[p]||^2 + REG) ======
__global__ void k_final(const float* __restrict__ Dm, float* __restrict__ out) {
    __shared__ float sh_a[8], sh_d[8];
    int p = blockIdx.x;
    int tx = threadIdx.x, lane = tx & 31, w = tx >> 5;
    float cf[ORDER];
    #pragma unroll
    for (int l = 0; l < ORDER; l++) cf[l] = g_coeffs[l];
    const float* Dp = Dm + (size_t)p * D_FEAT;
    float acc = 0.f, den = 0.f;
    for (int d = tx; d < D_FEAT; d += NW) {
        float dir = 0.f;
        #pragma unroll
        for (int l = 0; l < ORDER; l++) dir = fmaf(cf[l], g_Q[(size_t)l * D_FEAT + d], dir);
        float dv = Dp[d];
        acc = fmaf(dv, dir, acc);
        den = fmaf(dv, dv, den);
    }
    #pragma unroll
    for (int o = 16; o; o >>= 1) {
        acc += __shfl_xor_sync(0xffffffffu, acc, o);
        den += __shfl_xor_sync(0xffffffffu, den, o);
    }
    if (lane == 0) { sh_a[w] = acc; sh_d[w] = den; }
    __syncthreads();
    if (tx == 0) {
        float A = 0.f, Dd = 0.f;
        #pragma unroll
        for (int i = 0; i < 8; i++) { A += sh_a[i]; Dd += sh_d[i]; }
        out[p] = A / (Dd + REG);
    }
}

// --------------------------------- launcher ----------------------------------
extern "C" void kernel_launch(void* const* d_in, const int* in_sizes, int n_in,
                              void* d_out, int out_size) {
    (void)out_size;
    const float* f = nullptr;
    const float* R = nullptr;
    const float* Dm = nullptr;
    for (int i = 0; i < n_in; i++) {
        if (in_sizes[i] == D_FEAT)               f  = (const float*)d_in[i];
        else if (in_sizes[i] == T_RES * D_FEAT)  R  = (const float*)d_in[i];
        else if (in_sizes[i] == ORDER * D_FEAT)  Dm = (const float*)d_in[i];
    }

    k_row_f<<<ROW_BLOCKS, NW>>>(R, f);
    k_prologue_col<<<COL_BLOCKS, NW>>>(R, f);
    for (int j = 0; j < ORDER; j++) {
        k_A<<<ROW_BLOCKS, NW>>>(R, j);
        k_B<<<COL_BLOCKS, NW>>>(R, j, (j == ORDER - 1) ? 1 : 0);
    }
    k_expmT<<<1, 32>>>();
    k_final<<<ORDER, NW>>>(Dm, (float*)d_out);
}